// round 11
// baseline (speedup 1.0000x reference)
#include <cuda_runtime.h>
#include <cuda_fp16.h>
#include <cstdint>

#define SEQ 512
#define BATCH 256
#define EMB 300
#define HID 10
#define G3 30
#define CHUNK 32
#define NCH 16
#define NKT 19                  // k-tiles of 16: covers k 0..303

// SMEM layout (bytes)
#define X32_OFF  0
#define X32_SLOT 38400          // 32 rows x 300 fp32; slots: (bt*2 + parity)
#define A_STRIDE 656            // 328 halves/row (304 used + pad), LDSM-friendly
#define A_SLOT   (32 * A_STRIDE)              // 20992; one per bt
#define A_OFF    (4 * X32_SLOT)               // 153600
#define GI_STRIDE 34
#define GI_SLOT  (32 * GI_STRIDE * 4)         // 4352; slots: (bt*2 + parity)
#define GI_OFF   (A_OFF + 2 * A_SLOT)         // 195584
#define SMEM_B   (GI_OFF + 4 * GI_SLOT)       // 212992

// W_ih_f pre-packed as mma.sync B-fragments: [nh][kt][nt][j][lane]
__device__ uint32_t g_bf[2 * NKT * 2 * 2 * 32];

// ---------- helpers ----------
__device__ __forceinline__ float tanha(float x) {
    float y;
    asm("tanh.approx.f32 %0, %1;" : "=f"(y) : "f"(x));
    return y;
}
__device__ __forceinline__ float sig_full(float x) {
    return fmaf(tanha(0.5f * x), 0.5f, 0.5f);
}
__device__ __forceinline__ uint32_t s2u(const void* p) {
    uint32_t a;
    asm("{ .reg .u64 t; cvta.to.shared.u64 t, %1; cvt.u32.u64 %0, t; }"
        : "=r"(a) : "l"(p));
    return a;
}
__device__ __forceinline__ void cpa16(uint32_t dst, const void* src) {
    asm volatile("cp.async.cg.shared.global [%0], [%1], 16;"
                 :: "r"(dst), "l"(src) : "memory");
}
__device__ __forceinline__ void cpa_commit() {
    asm volatile("cp.async.commit_group;" ::: "memory");
}
__device__ __forceinline__ void cpa_wait1() {
    asm volatile("cp.async.wait_group 1;" ::: "memory");
}
__device__ __forceinline__ void cpa_wait0() {
    asm volatile("cp.async.wait_group 0;" ::: "memory");
}
__device__ __forceinline__ void ldsm4(uint32_t& a0, uint32_t& a1,
                                      uint32_t& a2, uint32_t& a3, uint32_t addr) {
    asm volatile("ldmatrix.sync.aligned.m8n8.x4.shared.b16 {%0,%1,%2,%3}, [%4];"
                 : "=r"(a0), "=r"(a1), "=r"(a2), "=r"(a3) : "r"(addr));
}
__device__ __forceinline__ void mma16816(float* d, uint32_t a0, uint32_t a1,
                                         uint32_t a2, uint32_t a3,
                                         uint32_t b0, uint32_t b1) {
    asm volatile(
        "mma.sync.aligned.m16n8k16.row.col.f32.f16.f16.f32 "
        "{%0,%1,%2,%3}, {%4,%5,%6,%7}, {%8,%9}, {%0,%1,%2,%3};"
        : "+f"(d[0]), "+f"(d[1]), "+f"(d[2]), "+f"(d[3])
        : "r"(a0), "r"(a1), "r"(a2), "r"(a3), "r"(b0), "r"(b1));
}

// ---------- prep: W_ih_f -> fp16 B fragments (rows<20 pre-scaled 0.5) -------
__global__ void k_prepB(const float* __restrict__ w) {
    int i = blockIdx.x * 256 + threadIdx.x;
    if (i >= 2 * NKT * 2 * 2 * 32) return;
    int lane = i & 31;
    int t = i >> 5;
    int j  = t & 1;  t >>= 1;
    int nt = t & 1;  t >>= 1;
    int kt = t % NKT;
    int nh = t / NKT;
    int n = nh * 16 + nt * 8 + (lane >> 2);
    int k = kt * 16 + (lane & 3) * 2 + j * 8;
    float sc = (n < 20) ? 0.5f : 1.0f;
    float w0 = (n < G3 && k < EMB)     ? sc * w[n * EMB + k]     : 0.0f;
    float w1 = (n < G3 && k + 1 < EMB) ? sc * w[n * EMB + k + 1] : 0.0f;
    __half2 h = __floats2half2_rn(w0, w1);
    g_bf[i] = *(uint32_t*)&h;
}

// ---------- fused kernel: 192 threads, 1 block = 2 batch elements ----------
// wid 0-3: producers (bt = wid>>1, nh = wid&1): cp.async x, convert, HMMA gi
// wid 4,5: recurrence consumers (batch 0 / 1) — per-j gate scheme
__global__ void __launch_bounds__(192, 1) k_fused(
    const float* __restrict__ x,
    const float* __restrict__ b_ihf,
    const float* __restrict__ w_ihb, const float* __restrict__ b_ihb,
    const float* __restrict__ whh,  const float* __restrict__ bhhf,
    const float* __restrict__ bhhb, const float* __restrict__ wlin,
    const float* __restrict__ blin, float* __restrict__ out)
{
    extern __shared__ char smc[];
    const uint32_t sbase = s2u(smc);
    const int tid  = threadIdx.x;
    const int wid  = tid >> 5;
    const int lane = tid & 31;
    const int b0   = blockIdx.x * 2;
    const unsigned mfull = 0xffffffffu;

    const bool is_rec = (wid >= 4);
    const int bt = is_rec ? (wid - 4) : (wid >> 1);
    const int nh = wid & 1;

    // zero A slots once (pad cols 300-327 must stay 0; convert rewrites 0-299)
    {
        uint4 z = make_uint4(0, 0, 0, 0);
        uint4* sA = (uint4*)(smc + A_OFF);
        for (int i = tid; i < (2 * A_SLOT) / 16; i += 192) sA[i] = z;
    }

    // ---- producer setup: persistent B fragments + prologue cp.async ----
    uint32_t bf[NKT][2][2];
    if (!is_rec) {
        const uint32_t* gB = g_bf + nh * (NKT * 2 * 2 * 32);
#pragma unroll
        for (int kt = 0; kt < NKT; ++kt)
#pragma unroll
            for (int nt = 0; nt < 2; ++nt)
#pragma unroll
                for (int j = 0; j < 2; ++j)
                    bf[kt][nt][j] =
                        __ldg(gB + ((kt * 2 + nt) * 2 + j) * 32 + lane);

        const float4* src = (const float4*)(x +
            ((size_t)(b0 + bt) * SEQ + nh * 16) * EMB);
        uint32_t dst = sbase + X32_OFF + (bt * 2 + 0) * X32_SLOT + nh * 16 * 1200;
        for (int i = lane; i < 1200; i += 32) cpa16(dst + i * 16, src + i);
        cpa_commit();
    }

    // ---- rec setup: per-j gate rows + combined biases + bwd-dir gi dot ----
    const int l   = lane;
    const int l30 = (l < G3) ? l : 0;
    const int j10 = (l < HID) ? l : 0;
    float gb = 0.0f;
    float wr[HID], wz[HID], wn[HID];
    float cbr = 0.0f, cbz = 0.0f, bin = 0.0f, bhn = 0.0f;
    float h[HID], hj = 0.0f;

    if (is_rec) {
        const int b = b0 + bt;
        const float4* xq = (const float4*)(x + ((size_t)b * SEQ + SEQ - 1) * EMB);
        const float4* wq = (const float4*)(w_ihb + (size_t)l30 * EMB);
        float a0 = 0, a1 = 0, a2 = 0, a3 = 0;
#pragma unroll 5
        for (int k4 = 0; k4 < EMB / 4; ++k4) {
            float4 xv = __ldg(xq + k4);
            float4 wv4 = __ldg(wq + k4);
            a0 = fmaf(xv.x, wv4.x, a0);
            a1 = fmaf(xv.y, wv4.y, a1);
            a2 = fmaf(xv.z, wv4.z, a2);
            a3 = fmaf(xv.w, wv4.w, a3);
        }
        gb = (a0 + a1) + (a2 + a3) + ((l < G3) ? __ldg(b_ihb + l) : 0.0f);

#pragma unroll
        for (int k = 0; k < HID; ++k) {
            wr[k] = 0.0f; wz[k] = 0.0f; wn[k] = 0.0f; h[k] = 0.0f;
        }
        if (l < HID) {
#pragma unroll
            for (int k = 0; k < HID; ++k) {
                wr[k] = 0.5f * __ldg(whh + l * HID + k);
                wz[k] = 0.5f * __ldg(whh + (l + HID) * HID + k);
                wn[k] = __ldg(whh + (l + 2 * HID) * HID + k);
            }
            cbr = 0.5f * (__ldg(b_ihf + l)       + __ldg(bhhf + l));
            cbz = 0.5f * (__ldg(b_ihf + l + 10)  + __ldg(bhhf + l + 10));
            bin = __ldg(b_ihf + l + 20);
            bhn = __ldg(bhhf + l + 20);
        }
    }

    __syncthreads();

    // ---- lockstep: cpasync(p+1) | convert(p)+HMMA(p) | consume(p-1) ----
    for (int p = 0; p <= NCH; ++p) {
        if (!is_rec) {
            if (p + 1 < NCH) {
                const float4* src = (const float4*)(x +
                    ((size_t)(b0 + bt) * SEQ + (size_t)(p + 1) * CHUNK + nh * 16) * EMB);
                uint32_t dst = sbase + X32_OFF
                    + (bt * 2 + ((p + 1) & 1)) * X32_SLOT + nh * 16 * 1200;
                for (int i = lane; i < 1200; i += 32) cpa16(dst + i * 16, src + i);
                cpa_commit();
            }

            if (p < NCH) {
                if (p + 1 < NCH) cpa_wait1(); else cpa_wait0();

                const float4* xs = (const float4*)(smc + X32_OFF
                    + (bt * 2 + (p & 1)) * X32_SLOT + nh * 16 * 1200);
                char* aslot = smc + A_OFF + bt * A_SLOT;
#pragma unroll 4
                for (int i = lane; i < 16 * 75; i += 32) {
                    int row = i / 75, q = i - row * 75;
                    float4 v = xs[i];
                    __half2 h0 = __floats2half2_rn(v.x, v.y);
                    __half2 h1 = __floats2half2_rn(v.z, v.w);
                    *(uint2*)(aslot + (nh * 16 + row) * A_STRIDE + q * 8) =
                        make_uint2(*(uint32_t*)&h0, *(uint32_t*)&h1);
                }

                asm volatile("bar.sync %0, 64;" :: "r"(1 + bt) : "memory");

                const uint32_t abase = sbase + A_OFF + bt * A_SLOT;
                float* gis = (float*)(smc + GI_OFF + (bt * 2 + (p & 1)) * GI_SLOT);
                const int mi = lane >> 3, r = lane & 7;

                float d[2][2][4];
#pragma unroll
                for (int mt = 0; mt < 2; ++mt)
#pragma unroll
                    for (int nt = 0; nt < 2; ++nt)
#pragma unroll
                        for (int e = 0; e < 4; ++e) d[mt][nt][e] = 0.0f;

#pragma unroll
                for (int kt = 0; kt < NKT; ++kt) {
#pragma unroll
                    for (int mt = 0; mt < 2; ++mt) {
                        uint32_t addr = abase
                            + (mt * 16 + (mi & 1) * 8 + r) * A_STRIDE
                            + (mi >> 1) * 16 + kt * 32;
                        uint32_t a0, a1, a2, a3;
                        ldsm4(a0, a1, a2, a3, addr);
                        mma16816(d[mt][0], a0, a1, a2, a3,
                                 bf[kt][0][0], bf[kt][0][1]);
                        mma16816(d[mt][1], a0, a1, a2, a3,
                                 bf[kt][1][0], bf[kt][1][1]);
                    }
                }

                const int rq = lane >> 2, cq = (lane & 3) * 2;
#pragma unroll
                for (int mt = 0; mt < 2; ++mt)
#pragma unroll
                    for (int nt = 0; nt < 2; ++nt) {
                        int col = nh * 16 + nt * 8 + cq;
                        *(float2*)(gis + (mt * 16 + rq) * GI_STRIDE + col) =
                            make_float2(d[mt][nt][0], d[mt][nt][1]);
                        *(float2*)(gis + (mt * 16 + rq + 8) * GI_STRIDE + col) =
                            make_float2(d[mt][nt][2], d[mt][nt][3]);
                    }
            }
        }

        // consumer: run chunk p-1, per-j scheme (lane j<10 owns gates j,j+10,j+20)
        if (is_rec && p >= 1) {
            const int c = p - 1;
            const float* gis =
                (const float*)(smc + GI_OFF + (bt * 2 + (c & 1)) * GI_SLOT);
            float gr = gis[j10], gz = gis[j10 + 10], gn = gis[j10 + 20];
#pragma unroll 4
            for (int u = 0; u < CHUNK; ++u) {
                int un = (u + 1 < CHUNK) ? u + 1 : u;
                const float* gnx = gis + un * GI_STRIDE;
                float gr2 = gnx[j10], gz2 = gnx[j10 + 10], gn2 = gnx[j10 + 20];

                // three dots, 2 accumulators each, consume h in arrival order
                float ar0 = gr + cbr, ar1 = 0.0f;
                float az0 = gz + cbz, az1 = 0.0f;
                float ah0 = bhn,      ah1 = 0.0f;
#pragma unroll
                for (int k = 0; k < HID; k += 2) {
                    ar0 = fmaf(h[k],     wr[k],     ar0);
                    az0 = fmaf(h[k],     wz[k],     az0);
                    ah0 = fmaf(h[k],     wn[k],     ah0);
                    ar1 = fmaf(h[k + 1], wr[k + 1], ar1);
                    az1 = fmaf(h[k + 1], wz[k + 1], az1);
                    ah1 = fmaf(h[k + 1], wn[k + 1], ah1);
                }

                float r  = fmaf(tanha(ar0 + ar1), 0.5f, 0.5f);
                float z  = fmaf(tanha(az0 + az1), 0.5f, 0.5f);
                float n  = tanha(fmaf(r, ah0 + ah1, gn + bin));
                float hn = fmaf(z, hj - n, n);

#pragma unroll
                for (int k = 0; k < HID; ++k) h[k] = __shfl_sync(mfull, hn, k);
                hj = hn;
                gr = gr2; gz = gz2; gn = gn2;
            }
        }

        __syncthreads();
    }

    // ---- epilogue: backward single step + linear head ----
    if (is_rec) {
        float bb  = (l < G3) ? __ldg(bhhb + l) : 0.0f;
        float sb  = gb + bb;
        float azb = __shfl_sync(mfull, sb, l + 10);
        float gbn = __shfl_sync(mfull, gb, l + 20);
        float bbn = __shfl_sync(mfull, bb, l + 20);
        float rb  = sig_full(sb);
        float zb  = sig_full(azb);
        float nb  = tanha(fmaf(rb, bbn, gbn));
        float hbv = (1.0f - zb) * nb;

        float cacc = 0.0f;
        if (l < HID) cacc = __ldg(wlin + l) * hj + __ldg(wlin + HID + l) * hbv;
        cacc += __shfl_down_sync(mfull, cacc, 8);
        cacc += __shfl_down_sync(mfull, cacc, 4);
        cacc += __shfl_down_sync(mfull, cacc, 2);
        cacc += __shfl_down_sync(mfull, cacc, 1);
        if (l == 0) out[b0 + bt] = cacc + __ldg(blin);
    }
}

extern "C" void kernel_launch(void* const* d_in, const int* in_sizes, int n_in,
                              void* d_out, int out_size)
{
    const float* x      = (const float*)d_in[0];
    const float* w_ih_f = (const float*)d_in[1];
    const float* w_hh_f = (const float*)d_in[2];
    const float* b_ih_f = (const float*)d_in[3];
    const float* b_hh_f = (const float*)d_in[4];
    const float* w_ih_b = (const float*)d_in[5];
    /* w_hh_b (d_in[6]) mathematically unused: h0 = 0 for the single bwd step */
    const float* b_ih_b = (const float*)d_in[7];
    const float* b_hh_b = (const float*)d_in[8];
    const float* w_lin  = (const float*)d_in[9];
    const float* b_lin  = (const float*)d_in[10];
    float* out = (float*)d_out;

    k_prepB<<<(2 * NKT * 2 * 2 * 32 + 255) / 256, 256>>>(w_ih_f);

    cudaFuncSetAttribute(k_fused, cudaFuncAttributeMaxDynamicSharedMemorySize,
                         SMEM_B);
    k_fused<<<BATCH / 2, 192, SMEM_B>>>(x, b_ih_f, w_ih_b, b_ih_b,
                                        w_hh_f, b_hh_f, b_hh_b, w_lin, b_lin,
                                        out);
}

// round 12
// speedup vs baseline: 1.0940x; 1.0940x over previous
#include <cuda_runtime.h>
#include <cuda_fp16.h>
#include <cstdint>

#define SEQ 512
#define BATCH 256
#define EMB 300
#define HID 10
#define G3 30
#define CHUNK 32
#define NCH 16
#define NKT 19                  // k-tiles of 16: covers k 0..303

// SMEM layout (bytes)
#define X32_OFF  0
#define X32_SLOT 38400          // 32 rows x 300 fp32; slots: (bt*2 + parity)
#define A_STRIDE 656            // 328 halves/row (304 used + pad), LDSM-friendly
#define A_SLOT   (32 * A_STRIDE)              // 20992; one per bt
#define A_OFF    (4 * X32_SLOT)               // 153600
#define GI_STRIDE 34
#define GI_SLOT  4608                          // 33 rows (32 + 1 pad) x 34 fl, padded
#define GI_OFF   (A_OFF + 2 * A_SLOT)         // 195584
#define SMEM_B   (GI_OFF + 4 * GI_SLOT)       // 214016

// W_ih_f pre-packed as mma.sync B-fragments: [nh][kt][nt][j][lane]
__device__ uint32_t g_bf[2 * NKT * 2 * 2 * 32];

// ---------- helpers ----------
__device__ __forceinline__ float tanha(float x) {
    float y;
    asm("tanh.approx.f32 %0, %1;" : "=f"(y) : "f"(x));
    return y;
}
__device__ __forceinline__ float sig_full(float x) {
    return fmaf(tanha(0.5f * x), 0.5f, 0.5f);
}
__device__ __forceinline__ uint32_t s2u(const void* p) {
    uint32_t a;
    asm("{ .reg .u64 t; cvta.to.shared.u64 t, %1; cvt.u32.u64 %0, t; }"
        : "=r"(a) : "l"(p));
    return a;
}
__device__ __forceinline__ unsigned long long pk2(float lo, float hi) {
    unsigned long long r;
    asm("mov.b64 %0, {%1, %2};" : "=l"(r) : "f"(lo), "f"(hi));
    return r;
}
__device__ __forceinline__ void upk2(unsigned long long v, float& lo, float& hi) {
    asm("mov.b64 {%0, %1}, %2;" : "=f"(lo), "=f"(hi) : "l"(v));
}
__device__ __forceinline__ unsigned long long fma2(unsigned long long a,
                                                   unsigned long long b,
                                                   unsigned long long c) {
    unsigned long long d;
    asm("fma.rn.f32x2 %0, %1, %2, %3;" : "=l"(d) : "l"(a), "l"(b), "l"(c));
    return d;
}
__device__ __forceinline__ void cpa16(uint32_t dst, const void* src) {
    asm volatile("cp.async.cg.shared.global [%0], [%1], 16;"
                 :: "r"(dst), "l"(src) : "memory");
}
__device__ __forceinline__ void cpa_commit() {
    asm volatile("cp.async.commit_group;" ::: "memory");
}
__device__ __forceinline__ void cpa_wait1() {
    asm volatile("cp.async.wait_group 1;" ::: "memory");
}
__device__ __forceinline__ void cpa_wait0() {
    asm volatile("cp.async.wait_group 0;" ::: "memory");
}
__device__ __forceinline__ void ldsm4(uint32_t& a0, uint32_t& a1,
                                      uint32_t& a2, uint32_t& a3, uint32_t addr) {
    asm volatile("ldmatrix.sync.aligned.m8n8.x4.shared.b16 {%0,%1,%2,%3}, [%4];"
                 : "=r"(a0), "=r"(a1), "=r"(a2), "=r"(a3) : "r"(addr));
}
__device__ __forceinline__ void mma16816(float* d, uint32_t a0, uint32_t a1,
                                         uint32_t a2, uint32_t a3,
                                         uint32_t b0, uint32_t b1) {
    asm volatile(
        "mma.sync.aligned.m16n8k16.row.col.f32.f16.f16.f32 "
        "{%0,%1,%2,%3}, {%4,%5,%6,%7}, {%8,%9}, {%0,%1,%2,%3};"
        : "+f"(d[0]), "+f"(d[1]), "+f"(d[2]), "+f"(d[3])
        : "r"(a0), "r"(a1), "r"(a2), "r"(a3), "r"(b0), "r"(b1));
}

// ---------- prep: W_ih_f -> fp16 B fragments (rows<20 pre-scaled 0.5) -------
__global__ void k_prepB(const float* __restrict__ w) {
    int i = blockIdx.x * 256 + threadIdx.x;
    if (i >= 2 * NKT * 2 * 2 * 32) return;
    int lane = i & 31;
    int t = i >> 5;
    int j  = t & 1;  t >>= 1;
    int nt = t & 1;  t >>= 1;
    int kt = t % NKT;
    int nh = t / NKT;
    int n = nh * 16 + nt * 8 + (lane >> 2);
    int k = kt * 16 + (lane & 3) * 2 + j * 8;
    float sc = (n < 20) ? 0.5f : 1.0f;
    float w0 = (n < G3 && k < EMB)     ? sc * w[n * EMB + k]     : 0.0f;
    float w1 = (n < G3 && k + 1 < EMB) ? sc * w[n * EMB + k + 1] : 0.0f;
    __half2 h = __floats2half2_rn(w0, w1);
    g_bf[i] = *(uint32_t*)&h;
}

// ---------- fused kernel: 192 threads (6 warps), 1 block = 2 batches -------
// wid 0,1: producers bt0 (nh 0,1) | wid 4,5: producers bt1 (nh 0,1)
// wid 2: rec bt0 | wid 3: rec bt1  -> each rec warp ALONE on SMSP 2 / 3
__global__ void __launch_bounds__(192, 1) k_fused(
    const float* __restrict__ x,
    const float* __restrict__ b_ihf,
    const float* __restrict__ w_ihb, const float* __restrict__ b_ihb,
    const float* __restrict__ whh,  const float* __restrict__ bhhf,
    const float* __restrict__ bhhb, const float* __restrict__ wlin,
    const float* __restrict__ blin, float* __restrict__ out)
{
    extern __shared__ char smc[];
    const uint32_t sbase = s2u(smc);
    const int tid  = threadIdx.x;
    const int wid  = tid >> 5;
    const int lane = tid & 31;
    const int b0   = blockIdx.x * 2;
    const unsigned mfull = 0xffffffffu;

    const bool is_rec = (wid == 2) || (wid == 3);
    const int bt = is_rec ? (wid - 2) : ((wid >= 4) ? 1 : 0);
    const int nh = wid & 1;

    // zero A slots once (pad cols 300-327 must stay 0; convert rewrites 0-299)
    {
        uint4 z = make_uint4(0, 0, 0, 0);
        uint4* sA = (uint4*)(smc + A_OFF);
        for (int i = tid; i < (2 * A_SLOT) / 16; i += 192) sA[i] = z;
    }

    // ---- producer setup: persistent B fragments + prologue cp.async ----
    uint32_t bf[NKT][2][2];
    if (!is_rec) {
        const uint32_t* gB = g_bf + nh * (NKT * 2 * 2 * 32);
#pragma unroll
        for (int kt = 0; kt < NKT; ++kt)
#pragma unroll
            for (int nt = 0; nt < 2; ++nt)
#pragma unroll
                for (int j = 0; j < 2; ++j)
                    bf[kt][nt][j] =
                        __ldg(gB + ((kt * 2 + nt) * 2 + j) * 32 + lane);

        const float4* src = (const float4*)(x +
            ((size_t)(b0 + bt) * SEQ + nh * 16) * EMB);
        uint32_t dst = sbase + X32_OFF + (bt * 2 + 0) * X32_SLOT + nh * 16 * 1200;
        for (int i = lane; i < 1200; i += 32) cpa16(dst + i * 16, src + i);
        cpa_commit();
    }

    // ---- rec setup: per-j f32x2 gate rows + biases + bwd-dir gi dot ----
    const int l   = lane;
    const int l30 = (l < G3) ? l : 0;
    const int j10 = (l < HID) ? l : 0;
    float gb = 0.0f;
    unsigned long long wr2[5], wz2[5], wn2[5];
    float cbr = 0.0f, cbz = 0.0f, bin_ = 0.0f, hbn2 = 0.0f;
    float hj = 0.0f;

    if (is_rec) {
        const int b = b0 + bt;
        const float4* xq = (const float4*)(x + ((size_t)b * SEQ + SEQ - 1) * EMB);
        const float4* wq = (const float4*)(w_ihb + (size_t)l30 * EMB);
        float a0 = 0, a1 = 0, a2 = 0, a3 = 0;
#pragma unroll 5
        for (int k4 = 0; k4 < EMB / 4; ++k4) {
            float4 xv = __ldg(xq + k4);
            float4 wv4 = __ldg(wq + k4);
            a0 = fmaf(xv.x, wv4.x, a0);
            a1 = fmaf(xv.y, wv4.y, a1);
            a2 = fmaf(xv.z, wv4.z, a2);
            a3 = fmaf(xv.w, wv4.w, a3);
        }
        gb = (a0 + a1) + (a2 + a3) + ((l < G3) ? __ldg(b_ihb + l) : 0.0f);

#pragma unroll
        for (int k = 0; k < 5; ++k) { wr2[k] = 0; wz2[k] = 0; wn2[k] = 0; }
        if (l < HID) {
#pragma unroll
            for (int k = 0; k < 5; ++k) {
                wr2[k] = pk2(0.5f * __ldg(whh + l * HID + 2 * k),
                             0.5f * __ldg(whh + l * HID + 2 * k + 1));
                wz2[k] = pk2(0.5f * __ldg(whh + (l + 10) * HID + 2 * k),
                             0.5f * __ldg(whh + (l + 10) * HID + 2 * k + 1));
                wn2[k] = pk2(0.5f * __ldg(whh + (l + 20) * HID + 2 * k),
                             0.5f * __ldg(whh + (l + 20) * HID + 2 * k + 1));
            }
            cbr  = 0.5f * (__ldg(b_ihf + l)      + __ldg(bhhf + l));
            cbz  = 0.5f * (__ldg(b_ihf + l + 10) + __ldg(bhhf + l + 10));
            bin_ = __ldg(b_ihf + l + 20);
            hbn2 = 0.5f * __ldg(bhhf + l + 20);
        }
    }

    __syncthreads();

    // ---- lockstep: cpasync(p+1) | convert(p)+HMMA(p) | consume(p-1) ----
    for (int p = 0; p <= NCH; ++p) {
        if (!is_rec) {
            if (p + 1 < NCH) {
                const float4* src = (const float4*)(x +
                    ((size_t)(b0 + bt) * SEQ + (size_t)(p + 1) * CHUNK + nh * 16) * EMB);
                uint32_t dst = sbase + X32_OFF
                    + (bt * 2 + ((p + 1) & 1)) * X32_SLOT + nh * 16 * 1200;
                for (int i = lane; i < 1200; i += 32) cpa16(dst + i * 16, src + i);
                cpa_commit();
            }

            if (p < NCH) {
                if (p + 1 < NCH) cpa_wait1(); else cpa_wait0();

                const float4* xs = (const float4*)(smc + X32_OFF
                    + (bt * 2 + (p & 1)) * X32_SLOT + nh * 16 * 1200);
                char* aslot = smc + A_OFF + bt * A_SLOT;
#pragma unroll 4
                for (int i = lane; i < 16 * 75; i += 32) {
                    int row = i / 75, q = i - row * 75;
                    float4 v = xs[i];
                    __half2 h0 = __floats2half2_rn(v.x, v.y);
                    __half2 h1 = __floats2half2_rn(v.z, v.w);
                    *(uint2*)(aslot + (nh * 16 + row) * A_STRIDE + q * 8) =
                        make_uint2(*(uint32_t*)&h0, *(uint32_t*)&h1);
                }

                asm volatile("bar.sync %0, 64;" :: "r"(1 + bt) : "memory");

                const uint32_t abase = sbase + A_OFF + bt * A_SLOT;
                float* gis = (float*)(smc + GI_OFF + (bt * 2 + (p & 1)) * GI_SLOT);
                const int mi = lane >> 3, r = lane & 7;

                float d[2][2][4];
#pragma unroll
                for (int mt = 0; mt < 2; ++mt)
#pragma unroll
                    for (int nt = 0; nt < 2; ++nt)
#pragma unroll
                        for (int e = 0; e < 4; ++e) d[mt][nt][e] = 0.0f;

#pragma unroll
                for (int kt = 0; kt < NKT; ++kt) {
#pragma unroll
                    for (int mt = 0; mt < 2; ++mt) {
                        uint32_t addr = abase
                            + (mt * 16 + (mi & 1) * 8 + r) * A_STRIDE
                            + (mi >> 1) * 16 + kt * 32;
                        uint32_t a0, a1, a2, a3;
                        ldsm4(a0, a1, a2, a3, addr);
                        mma16816(d[mt][0], a0, a1, a2, a3,
                                 bf[kt][0][0], bf[kt][0][1]);
                        mma16816(d[mt][1], a0, a1, a2, a3,
                                 bf[kt][1][0], bf[kt][1][1]);
                    }
                }

                const int rq = lane >> 2, cq = (lane & 3) * 2;
#pragma unroll
                for (int mt = 0; mt < 2; ++mt)
#pragma unroll
                    for (int nt = 0; nt < 2; ++nt) {
                        int col = nh * 16 + nt * 8 + cq;
                        *(float2*)(gis + (mt * 16 + rq) * GI_STRIDE + col) =
                            make_float2(d[mt][nt][0], d[mt][nt][1]);
                        *(float2*)(gis + (mt * 16 + rq + 8) * GI_STRIDE + col) =
                            make_float2(d[mt][nt][2], d[mt][nt][3]);
                    }
            }
        }

        // consumer: run chunk p-1, per-j with f32x2 dots
        if (is_rec && p >= 1) {
            const int c = p - 1;
            const float* gis =
                (const float*)(smc + GI_OFF + (bt * 2 + (c & 1)) * GI_SLOT);
            float grp = gis[j10]      + cbr;
            float gzp = gis[j10 + 10] + cbz;
            float gnp = gis[j10 + 20] + bin_;
#pragma unroll 4
            for (int u = 0; u < CHUNK; ++u) {
                // prefetch next step's gi (padded row at u+1 == 32)
                const float* gx = gis + (u + 1) * GI_STRIDE;
                float grn = gx[j10], gzn = gx[j10 + 10], gnn = gx[j10 + 20];

                // broadcast h (lane j owns h[j])
                unsigned long long h2[5];
#pragma unroll
                for (int k = 0; k < 5; ++k) {
                    float lo = __shfl_sync(mfull, hj, 2 * k);
                    float hi = __shfl_sync(mfull, hj, 2 * k + 1);
                    h2[k] = pk2(lo, hi);
                }

                // three dots via f32x2, 2 chains each
                unsigned long long aR = fma2(h2[0], wr2[0], pk2(grp, 0.0f));
                unsigned long long bR = fma2(h2[1], wr2[1], 0ULL);
                unsigned long long aZ = fma2(h2[0], wz2[0], pk2(gzp, 0.0f));
                unsigned long long bZ = fma2(h2[1], wz2[1], 0ULL);
                unsigned long long aN = fma2(h2[0], wn2[0], pk2(hbn2, 0.0f));
                unsigned long long bN = fma2(h2[1], wn2[1], 0ULL);
                aR = fma2(h2[2], wr2[2], aR);  bR = fma2(h2[3], wr2[3], bR);
                aZ = fma2(h2[2], wz2[2], aZ);  bZ = fma2(h2[3], wz2[3], bZ);
                aN = fma2(h2[2], wn2[2], aN);  bN = fma2(h2[3], wn2[3], bN);
                aR = fma2(h2[4], wr2[4], aR);
                aZ = fma2(h2[4], wz2[4], aZ);
                aN = fma2(h2[4], wn2[4], aN);

                float x0, x1, y0, y1;
                upk2(aR, x0, x1); upk2(bR, y0, y1);
                float ar = (x0 + x1) + (y0 + y1);        // 0.5 * r-preact
                upk2(aZ, x0, x1); upk2(bZ, y0, y1);
                float az = (x0 + x1) + (y0 + y1);        // 0.5 * z-preact
                upk2(aN, x0, x1); upk2(bN, y0, y1);
                float ah = (x0 + x1) + (y0 + y1);        // 0.5 * (Wn h + bhn)

                float tr = tanha(ar);
                float tz = tanha(az);
                float base = gnp + ah;                   // gn + ah'
                float npre = fmaf(ah, tr, base);         // gn + r*(Wn h + bhn)
                float nn = tanha(npre);
                float z  = fmaf(tz, 0.5f, 0.5f);
                float zh  = z * hj;                      // parallel with tanh(npre)
                float omz = 1.0f - z;
                hj = fmaf(omz, nn, zh);

                grp = grn + cbr; gzp = gzn + cbz; gnp = gnn + bin_;
            }
        }

        __syncthreads();
    }

    // ---- epilogue: backward single step + linear head ----
    if (is_rec) {
        float bb  = (l < G3) ? __ldg(bhhb + l) : 0.0f;
        float sb  = gb + bb;
        float azb = __shfl_sync(mfull, sb, l + 10);
        float gbn = __shfl_sync(mfull, gb, l + 20);
        float bbn = __shfl_sync(mfull, bb, l + 20);
        float rb  = sig_full(sb);
        float zb  = sig_full(azb);
        float nb  = tanha(fmaf(rb, bbn, gbn));
        float hbv = (1.0f - zb) * nb;

        float cacc = 0.0f;
        if (l < HID) cacc = __ldg(wlin + l) * hj + __ldg(wlin + HID + l) * hbv;
        cacc += __shfl_down_sync(mfull, cacc, 8);
        cacc += __shfl_down_sync(mfull, cacc, 4);
        cacc += __shfl_down_sync(mfull, cacc, 2);
        cacc += __shfl_down_sync(mfull, cacc, 1);
        if (l == 0) out[b0 + bt] = cacc + __ldg(blin);
    }
}

extern "C" void kernel_launch(void* const* d_in, const int* in_sizes, int n_in,
                              void* d_out, int out_size)
{
    const float* x      = (const float*)d_in[0];
    const float* w_ih_f = (const float*)d_in[1];
    const float* w_hh_f = (const float*)d_in[2];
    const float* b_ih_f = (const float*)d_in[3];
    const float* b_hh_f = (const float*)d_in[4];
    const float* w_ih_b = (const float*)d_in[5];
    /* w_hh_b (d_in[6]) mathematically unused: h0 = 0 for the single bwd step */
    const float* b_ih_b = (const float*)d_in[7];
    const float* b_hh_b = (const float*)d_in[8];
    const float* w_lin  = (const float*)d_in[9];
    const float* b_lin  = (const float*)d_in[10];
    float* out = (float*)d_out;

    k_prepB<<<(2 * NKT * 2 * 2 * 32 + 255) / 256, 256>>>(w_ih_f);

    cudaFuncSetAttribute(k_fused, cudaFuncAttributeMaxDynamicSharedMemorySize,
                         SMEM_B);
    k_fused<<<BATCH / 2, 192, SMEM_B>>>(x, b_ih_f, w_ih_b, b_ih_b,
                                        w_hh_f, b_hh_f, b_hh_b, w_lin, b_lin,
                                        out);
}